// round 7
// baseline (speedup 1.0000x reference)
#include <cuda_runtime.h>

// NeuralODE via exact linearity: x_k = Q^k x0, Q = (Tsit5 substep)^8.
// Register-carried propagator P = Q^{ka} (all propagators commute), updated
// per item by uniform Q^{+12} / Q^{-13}. No smem staging. x0 loads are
// software-pipelined (prefetch next item's x0 before storing the current),
// stores are fully coalesced STG.128. Fast path has zero per-item guards.

namespace {

constexpr int TRAJ  = 25;
constexpr int NSUB  = 8;
constexpr int BLOCK = 256;
constexpr int ITEMS = 8;     // float4 outputs per thread; item stride = BLOCK

struct M2 { float a, b, c, d; };

__device__ __forceinline__ M2 m2mul(const M2& x, const M2& y) {
    M2 r;
    r.a = fmaf(x.a, y.a, x.b * y.c);
    r.b = fmaf(x.a, y.b, x.b * y.d);
    r.c = fmaf(x.c, y.a, x.d * y.c);
    r.d = fmaf(x.c, y.b, x.d * y.d);
    return r;
}

__device__ __forceinline__ M2 stageY(float h, const M2* K, const float* c, int n) {
    M2 r = {1.f, 0.f, 0.f, 1.f};
    for (int i = 0; i < n; ++i) {
        float s = h * c[i];
        r.a = fmaf(s, K[i].a, r.a);
        r.b = fmaf(s, K[i].b, r.b);
        r.c = fmaf(s, K[i].c, r.c);
        r.d = fmaf(s, K[i].d, r.d);
    }
    return r;
}

__global__ void __launch_bounds__(BLOCK)
ode_kernel(const float* __restrict__ x0s,
           const float* __restrict__ matrix,
           const float* __restrict__ Tptr,
           float4* __restrict__ out4,
           int n4, long long out_elems, float tailval)
{
    __shared__ float4 tbl[TRAJ + 3];  // [0..24]=Q^k, [25]=Q, [26]=Q^12, [27]=Q^-13

    if (threadIdx.x == 0) {
        // --- Tsit5 tableau (Tsitouras 2011) ---
        const float A21 = 0.161f;
        const float A31 = -0.008480655492356989f, A32 = 0.335480655492357f;
        const float A41 = 2.8971530571054935f, A42 = -6.359448489975075f,
                    A43 = 4.3622954328695815f;
        const float A51 = 5.325864828439257f, A52 = -11.748883564062828f,
                    A53 = 7.4955393428898365f, A54 = -0.09249506636175525f;
        const float A61 = 5.86145544294642f, A62 = -12.92096931784711f,
                    A63 = 8.159367898576159f, A64 = -0.071584973281401f,
                    A65 = -0.028269050394068383f;
        const float B1 = 0.09646076681806523f, B2 = 0.01f,
                    B3 = 0.4798896504144996f, B4 = 1.379008574103742f,
                    B5 = -3.290069515436081f, B6 = 2.324710524099774f;

        const float h = 1.0f / float((TRAJ - 1) * NSUB);
        const float T = Tptr[0];
        M2 A = { T * matrix[0], T * matrix[1], T * matrix[2], T * matrix[3] };

        M2 K[6];
        K[0] = A;
        { const float c[1] = {A21};                     K[1] = m2mul(A, stageY(h, K, c, 1)); }
        { const float c[2] = {A31, A32};                K[2] = m2mul(A, stageY(h, K, c, 2)); }
        { const float c[3] = {A41, A42, A43};           K[3] = m2mul(A, stageY(h, K, c, 3)); }
        { const float c[4] = {A51, A52, A53, A54};      K[4] = m2mul(A, stageY(h, K, c, 4)); }
        { const float c[5] = {A61, A62, A63, A64, A65}; K[5] = m2mul(A, stageY(h, K, c, 5)); }
        const float bb[6] = {B1, B2, B3, B4, B5, B6};
        M2 S = stageY(h, K, bb, 6);                           // one substep
        M2 Q = m2mul(S, S); Q = m2mul(Q, Q); Q = m2mul(Q, Q); // S^8

        M2 P = {1.f, 0.f, 0.f, 1.f};
        #pragma unroll 1
        for (int k = 0; k < TRAJ; ++k) {
            tbl[k] = make_float4(P.a, P.b, P.c, P.d);
            P = m2mul(Q, P);
        }
        M2 Q2  = m2mul(Q, Q);
        M2 Q4  = m2mul(Q2, Q2);
        M2 Q8  = m2mul(Q4, Q4);
        M2 Q12 = m2mul(Q8, Q4);
        M2 Q13 = m2mul(Q12, Q);
        const float invdet = 1.0f / (Q13.a * Q13.d - Q13.b * Q13.c);
        M2 QW = {  Q13.d * invdet, -Q13.b * invdet,
                  -Q13.c * invdet,  Q13.a * invdet };   // Q^-13

        tbl[25] = make_float4(Q.a, Q.b, Q.c, Q.d);
        tbl[26] = make_float4(Q12.a, Q12.b, Q12.c, Q12.d);
        tbl[27] = make_float4(QW.a, QW.b, QW.c, QW.d);
    }
    __syncthreads();

    const float4 fQ  = tbl[25];   // broadcast LDS -> registers
    const float4 fQF = tbl[26];
    const float4 fQW = tbl[27];

    const float2* __restrict__ x02 = reinterpret_cast<const float2*>(x0s);

    const int q0 = blockIdx.x * (BLOCK * ITEMS) + threadIdx.x;
    const int a0 = 2 * q0;
    unsigned pa = (unsigned)a0 / 25u;
    int ka = a0 - (int)(pa * 25u);

    float4 P  = tbl[ka];          // the only divergent LDS, once per thread
    float2 xa = __ldg(&x02[pa]);  // pipeline head

    const bool full = (q0 + (ITEMS - 1) * BLOCK) < n4;

    if (full) {
        #pragma unroll
        for (int i = 0; i < ITEMS; ++i) {
            const bool wrap = (ka >= 13);
            const unsigned pn = pa + (wrap ? 21u : 20u);
            const int      kn = ka + (wrap ? -13 : 12);

            // Prefetch next item's x0 (keeps 2 loads in flight).
            float2 xn = xa;
            if (i < ITEMS - 1) xn = __ldg(&x02[pn]);

            float4 r;
            r.x = fmaf(P.x, xa.x, P.y * xa.y);
            r.y = fmaf(P.z, xa.x, P.w * xa.y);
            if (ka == TRAJ - 1) {            // crossing: second sample is next x0
                const float2 xb = __ldg(&x02[pa + 1]);
                r.z = xb.x; r.w = xb.y;
            } else {
                r.z = fmaf(fQ.x, r.x, fQ.y * r.y);
                r.w = fmaf(fQ.z, r.x, fQ.w * r.y);
            }
            out4[q0 + i * BLOCK] = r;

            const float4 U = wrap ? fQW : fQF;   // P *= Q^12 or Q^-13 (commute)
            float4 Pn;
            Pn.x = fmaf(P.x, U.x, P.y * U.z);
            Pn.y = fmaf(P.x, U.y, P.y * U.w);
            Pn.z = fmaf(P.z, U.x, P.w * U.z);
            Pn.w = fmaf(P.z, U.y, P.w * U.w);
            P = Pn; xa = xn; ka = kn; pa = pn;
        }
    } else {
        #pragma unroll
        for (int i = 0; i < ITEMS; ++i) {
            const int q = q0 + i * BLOCK;
            if (q >= n4) break;
            const bool wrap = (ka >= 13);
            const unsigned pn = pa + (wrap ? 21u : 20u);
            const int      kn = ka + (wrap ? -13 : 12);

            float4 r;
            r.x = fmaf(P.x, xa.x, P.y * xa.y);
            r.y = fmaf(P.z, xa.x, P.w * xa.y);
            if (ka == TRAJ - 1) {
                const float2 xb = __ldg(&x02[pa + 1]);
                r.z = xb.x; r.w = xb.y;
            } else {
                r.z = fmaf(fQ.x, r.x, fQ.y * r.y);
                r.w = fmaf(fQ.z, r.x, fQ.w * r.y);
            }
            out4[q] = r;

            const float4 U = wrap ? fQW : fQF;
            float4 Pn;
            Pn.x = fmaf(P.x, U.x, P.y * U.z);
            Pn.y = fmaf(P.x, U.y, P.y * U.w);
            Pn.z = fmaf(P.z, U.x, P.w * U.z);
            Pn.w = fmaf(P.z, U.y, P.w * U.w);
            P = Pn; ka = kn; pa = pn;
            if (i < ITEMS - 1 && (int)pn * 1 >= 0) {
                const int qn = q0 + (i + 1) * BLOCK;
                if (qn < n4) xa = __ldg(&x02[pn]);
            }
        }
    }

    // Scalar tail (num_steps analog), exactly representable in fp32.
    if (blockIdx.x == 0 && threadIdx.x == 0) {
        float* out = reinterpret_cast<float*>(out4);
        for (long long i = (long long)n4 * 4; i < out_elems; ++i) out[i] = tailval;
    }
}

} // namespace

extern "C" void kernel_launch(void* const* d_in, const int* in_sizes, int n_in,
                              void* d_out, int out_size) {
    const float* x0s    = (const float*)d_in[0];
    const float* matrix = (const float*)d_in[1];
    const float* T      = (const float*)d_in[2];

    const int batch = in_sizes[0] / 2;                 // x0s is [batch,2]
    const long long n2 = (long long)batch * TRAJ;      // float2 outputs
    const int n4 = (int)(n2 / 2);                      // batch*25 even
    const float tail = (float)((long long)batch * (TRAJ - 1) * NSUB);

    const int per_block = BLOCK * ITEMS;
    const int grid = (n4 + per_block - 1) / per_block;

    ode_kernel<<<grid, BLOCK>>>(x0s, matrix, T, (float4*)d_out,
                                n4, (long long)out_size, tail);
}

// round 8
// speedup vs baseline: 1.0128x; 1.0128x over previous
#include <cuda_runtime.h>
#include <cstdint>

// NeuralODE via exact linearity: x_k = Q^k x0, Q = (Tsit5 substep)^8.
// R6 phased staging (best measured) + 256-bit flush stores (st.global.v8.f32,
// Blackwell STG.E.256): halves in-flight store entries and LSU issue slots
// for the same 105MB output stream.

namespace {

constexpr int TRAJ  = 25;
constexpr int NSUB  = 8;
constexpr int BLOCK = 256;
constexpr int HALF  = 128;                     // points staged per phase
constexpr int F4_PER_PHASE = HALF * TRAJ / 2;  // 1600 float4
constexpr int F8_PER_PHASE = F4_PER_PHASE / 2; // 800 float8 (32B)

struct M2 { float a, b, c, d; };

__device__ __forceinline__ M2 m2mul(const M2& x, const M2& y) {
    M2 r;
    r.a = fmaf(x.a, y.a, x.b * y.c);
    r.b = fmaf(x.a, y.b, x.b * y.d);
    r.c = fmaf(x.c, y.a, x.d * y.c);
    r.d = fmaf(x.c, y.b, x.d * y.d);
    return r;
}

__device__ __forceinline__ M2 stageY(float h, const M2* K, const float* c, int n) {
    M2 r = {1.f, 0.f, 0.f, 1.f};
    for (int i = 0; i < n; ++i) {
        float s = h * c[i];
        r.a = fmaf(s, K[i].a, r.a);
        r.b = fmaf(s, K[i].b, r.b);
        r.c = fmaf(s, K[i].c, r.c);
        r.d = fmaf(s, K[i].d, r.d);
    }
    return r;
}

__device__ __forceinline__ void stg256(float* gp, const float4& u, const float4& v) {
    asm volatile("st.global.v8.f32 [%0], {%1,%2,%3,%4,%5,%6,%7,%8};"
                 :: "l"(gp),
                    "f"(u.x), "f"(u.y), "f"(u.z), "f"(u.w),
                    "f"(v.x), "f"(v.y), "f"(v.z), "f"(v.w)
                 : "memory");
}

__global__ void __launch_bounds__(BLOCK)
ode_kernel(const float* __restrict__ x0s,
           const float* __restrict__ matrix,
           const float* __restrict__ Tptr,
           float* __restrict__ out,
           int batch, int n4, long long out_elems, float tailval)
{
    __shared__ float4 mats[TRAJ];           // Q^k table, 400 B
    __shared__ float2 stage[HALF * TRAJ];   // 25.6 KB phase tile

    if (threadIdx.x == 0) {
        // --- Tsit5 tableau (Tsitouras 2011) ---
        const float A21 = 0.161f;
        const float A31 = -0.008480655492356989f, A32 = 0.335480655492357f;
        const float A41 = 2.8971530571054935f, A42 = -6.359448489975075f,
                    A43 = 4.3622954328695815f;
        const float A51 = 5.325864828439257f, A52 = -11.748883564062828f,
                    A53 = 7.4955393428898365f, A54 = -0.09249506636175525f;
        const float A61 = 5.86145544294642f, A62 = -12.92096931784711f,
                    A63 = 8.159367898576159f, A64 = -0.071584973281401f,
                    A65 = -0.028269050394068383f;
        const float B1 = 0.09646076681806523f, B2 = 0.01f,
                    B3 = 0.4798896504144996f, B4 = 1.379008574103742f,
                    B5 = -3.290069515436081f, B6 = 2.324710524099774f;

        const float h = 1.0f / float((TRAJ - 1) * NSUB);
        const float T = Tptr[0];
        M2 A = { T * matrix[0], T * matrix[1], T * matrix[2], T * matrix[3] };

        M2 K[6];
        K[0] = A;
        { const float c[1] = {A21};                     K[1] = m2mul(A, stageY(h, K, c, 1)); }
        { const float c[2] = {A31, A32};                K[2] = m2mul(A, stageY(h, K, c, 2)); }
        { const float c[3] = {A41, A42, A43};           K[3] = m2mul(A, stageY(h, K, c, 3)); }
        { const float c[4] = {A51, A52, A53, A54};      K[4] = m2mul(A, stageY(h, K, c, 4)); }
        { const float c[5] = {A61, A62, A63, A64, A65}; K[5] = m2mul(A, stageY(h, K, c, 5)); }
        const float bb[6] = {B1, B2, B3, B4, B5, B6};
        M2 S = stageY(h, K, bb, 6);                          // one substep
        M2 Q = m2mul(S, S); Q = m2mul(Q, Q); Q = m2mul(Q, Q); // S^8

        M2 P = {1.f, 0.f, 0.f, 1.f};
        #pragma unroll 1
        for (int k = 0; k < TRAJ; ++k) {
            mats[k] = make_float4(P.a, P.b, P.c, P.d);
            P = m2mul(Q, P);
        }
    }
    __syncthreads();

    const float2* __restrict__ x02 = reinterpret_cast<const float2*>(x0s);
    const float4* __restrict__ st4 = reinterpret_cast<const float4*>(stage);
    const int half_id = threadIdx.x >> 7;          // 0 or 1
    const int lane128 = threadIdx.x & (HALF - 1);
    const int total8  = n4 >> 1;                   // n4 is even (batch even)

    #pragma unroll 1
    for (int ph = 0; ph < 2; ++ph) {
        // --- compute phase: 128 of the 256 threads stage their point ---
        if (half_id == ph) {
            const int point = blockIdx.x * BLOCK + ph * HALF + lane128;
            float2 xy = make_float2(0.f, 0.f);
            if (point < batch) xy = x02[point];
            #pragma unroll
            for (int k = 0; k < TRAJ; ++k) {
                const float4 m = mats[k];          // uniform k -> LDS broadcast
                stage[lane128 * TRAJ + k] =
                    make_float2(fmaf(m.x, xy.x, m.y * xy.y),
                                fmaf(m.z, xy.x, m.w * xy.y));
            }
        }
        __syncthreads();

        // --- flush phase: all 256 threads, contiguous 256-bit bursts ---
        const int base8 = blockIdx.x * (2 * F8_PER_PHASE) + ph * F8_PER_PHASE;
        #pragma unroll
        for (int i = 0; i < (F8_PER_PHASE + BLOCK - 1) / BLOCK; ++i) {
            const int f = i * BLOCK + threadIdx.x;
            const int g = base8 + f;
            if (f < F8_PER_PHASE && g < total8) {
                const float4 u = st4[2 * f];
                const float4 v = st4[2 * f + 1];
                stg256(out + (size_t)g * 8, u, v);
            }
        }
        __syncthreads();
    }

    // Scalar tail (num_steps analog), exactly representable in fp32.
    if (blockIdx.x == 0 && threadIdx.x == 0) {
        for (long long i = (long long)n4 * 4; i < out_elems; ++i) out[i] = tailval;
    }
}

} // namespace

extern "C" void kernel_launch(void* const* d_in, const int* in_sizes, int n_in,
                              void* d_out, int out_size) {
    const float* x0s    = (const float*)d_in[0];
    const float* matrix = (const float*)d_in[1];
    const float* T      = (const float*)d_in[2];

    const int batch = in_sizes[0] / 2;                 // x0s is [batch,2]
    const long long n2 = (long long)batch * TRAJ;      // float2 outputs
    const int n4 = (int)(n2 / 2);                      // batch*25 even
    const float tail = (float)((long long)batch * (TRAJ - 1) * NSUB);

    const int grid = (batch + BLOCK - 1) / BLOCK;
    ode_kernel<<<grid, BLOCK>>>(x0s, matrix, T, (float*)d_out,
                                batch, n4, (long long)out_size, tail);
}

// round 9
// speedup vs baseline: 1.0878x; 1.0741x over previous
#include <cuda_runtime.h>
#include <cstdint>

// NeuralODE via exact linearity: x_k = Q^k x0, Q = (Tsit5 substep)^8.
// Each block computes 256 points x 25 samples into a 51.2KB smem tile, then
// ships it to global with ONE cp.async.bulk (TMA path) — zero per-thread
// global stores, no L1tex store-queue occupancy.

namespace {

constexpr int TRAJ  = 25;
constexpr int NSUB  = 8;
constexpr int BLOCK = 256;
constexpr int TILE_BYTES = BLOCK * TRAJ * 8;   // 51200 B, 16B-multiple

struct M2 { float a, b, c, d; };

__device__ __forceinline__ M2 m2mul(const M2& x, const M2& y) {
    M2 r;
    r.a = fmaf(x.a, y.a, x.b * y.c);
    r.b = fmaf(x.a, y.b, x.b * y.d);
    r.c = fmaf(x.c, y.a, x.d * y.c);
    r.d = fmaf(x.c, y.b, x.d * y.d);
    return r;
}

__device__ __forceinline__ M2 stageY(float h, const M2* K, const float* c, int n) {
    M2 r = {1.f, 0.f, 0.f, 1.f};
    for (int i = 0; i < n; ++i) {
        float s = h * c[i];
        r.a = fmaf(s, K[i].a, r.a);
        r.b = fmaf(s, K[i].b, r.b);
        r.c = fmaf(s, K[i].c, r.c);
        r.d = fmaf(s, K[i].d, r.d);
    }
    return r;
}

__device__ __forceinline__ uint32_t smem_u32(const void* p) {
    return (uint32_t)__cvta_generic_to_shared(p);
}

__global__ void __launch_bounds__(BLOCK)
ode_kernel(const float* __restrict__ x0s,
           const float* __restrict__ matrix,
           const float* __restrict__ Tptr,
           float* __restrict__ out,
           int batch, long long out_elems, float tailval)
{
    __shared__ float4 mats[TRAJ];            // Q^k table, 400 B (static)
    extern __shared__ float2 stage[];        // 51.2 KB tile (dynamic)

    if (threadIdx.x == 0) {
        // --- Tsit5 tableau (Tsitouras 2011) ---
        const float A21 = 0.161f;
        const float A31 = -0.008480655492356989f, A32 = 0.335480655492357f;
        const float A41 = 2.8971530571054935f, A42 = -6.359448489975075f,
                    A43 = 4.3622954328695815f;
        const float A51 = 5.325864828439257f, A52 = -11.748883564062828f,
                    A53 = 7.4955393428898365f, A54 = -0.09249506636175525f;
        const float A61 = 5.86145544294642f, A62 = -12.92096931784711f,
                    A63 = 8.159367898576159f, A64 = -0.071584973281401f,
                    A65 = -0.028269050394068383f;
        const float B1 = 0.09646076681806523f, B2 = 0.01f,
                    B3 = 0.4798896504144996f, B4 = 1.379008574103742f,
                    B5 = -3.290069515436081f, B6 = 2.324710524099774f;

        const float h = 1.0f / float((TRAJ - 1) * NSUB);
        const float T = Tptr[0];
        M2 A = { T * matrix[0], T * matrix[1], T * matrix[2], T * matrix[3] };

        M2 K[6];
        K[0] = A;
        { const float c[1] = {A21};                     K[1] = m2mul(A, stageY(h, K, c, 1)); }
        { const float c[2] = {A31, A32};                K[2] = m2mul(A, stageY(h, K, c, 2)); }
        { const float c[3] = {A41, A42, A43};           K[3] = m2mul(A, stageY(h, K, c, 3)); }
        { const float c[4] = {A51, A52, A53, A54};      K[4] = m2mul(A, stageY(h, K, c, 4)); }
        { const float c[5] = {A61, A62, A63, A64, A65}; K[5] = m2mul(A, stageY(h, K, c, 5)); }
        const float bb[6] = {B1, B2, B3, B4, B5, B6};
        M2 S = stageY(h, K, bb, 6);                          // one substep
        M2 Q = m2mul(S, S); Q = m2mul(Q, Q); Q = m2mul(Q, Q); // S^8

        M2 P = {1.f, 0.f, 0.f, 1.f};
        #pragma unroll 1
        for (int k = 0; k < TRAJ; ++k) {
            mats[k] = make_float4(P.a, P.b, P.c, P.d);
            P = m2mul(Q, P);
        }
    }
    __syncthreads();

    const float2* __restrict__ x02 = reinterpret_cast<const float2*>(x0s);
    const int point = blockIdx.x * BLOCK + threadIdx.x;
    const int npts  = min(BLOCK, batch - blockIdx.x * BLOCK);   // full: 256

    float2 xy = make_float2(0.f, 0.f);
    if (point < batch) xy = x02[point];

    // All 256 threads stage their point's 25 samples (STS.64, 2-way conflict).
    #pragma unroll
    for (int k = 0; k < TRAJ; ++k) {
        const float4 m = mats[k];            // uniform k -> LDS broadcast
        stage[threadIdx.x * TRAJ + k] =
            make_float2(fmaf(m.x, xy.x, m.y * xy.y),
                        fmaf(m.z, xy.x, m.w * xy.y));
    }
    __syncthreads();

    float* gdst = out + (size_t)blockIdx.x * (BLOCK * TRAJ * 2);

    if (npts == BLOCK) {
        // One bulk async copy: smem tile -> contiguous global slice.
        if (threadIdx.x == 0) {
            asm volatile("fence.proxy.async.shared::cta;" ::: "memory");
            asm volatile(
                "cp.async.bulk.global.shared::cta.bulk_group [%0], [%1], %2;"
                :: "l"(gdst), "r"(smem_u32(stage)), "n"(TILE_BYTES)
                : "memory");
            asm volatile("cp.async.bulk.commit_group;" ::: "memory");
            asm volatile("cp.async.bulk.wait_group.read 0;" ::: "memory");
        }
        __syncthreads();   // keep smem alive until the bulk read completes
    } else if (npts > 0) {
        // Partial tail block (not hit for batch=2048*256): plain STG flush.
        const int nf4 = npts * TRAJ / 2;     // npts*25 float2 -> float4 pairs
        const float4* st4 = reinterpret_cast<const float4*>(stage);
        float4* g4 = reinterpret_cast<float4*>(gdst);
        for (int j = threadIdx.x; j < nf4; j += BLOCK) g4[j] = st4[j];
        if ((npts * TRAJ) & 1) {             // odd float2 count: last element
            if (threadIdx.x == 0)
                reinterpret_cast<float2*>(gdst)[npts * TRAJ - 1] =
                    stage[npts * TRAJ - 1];
        }
    }

    // Scalar tail (num_steps analog), exactly representable in fp32.
    if (blockIdx.x == 0 && threadIdx.x == 0) {
        const long long traj_elems = (long long)batch * TRAJ * 2;
        for (long long i = traj_elems; i < out_elems; ++i) out[i] = tailval;
    }
}

} // namespace

extern "C" void kernel_launch(void* const* d_in, const int* in_sizes, int n_in,
                              void* d_out, int out_size) {
    const float* x0s    = (const float*)d_in[0];
    const float* matrix = (const float*)d_in[1];
    const float* T      = (const float*)d_in[2];

    const int batch = in_sizes[0] / 2;                 // x0s is [batch,2]
    const float tail = (float)((long long)batch * (TRAJ - 1) * NSUB);

    static bool attr_done = false;   // idempotent attribute set (not a guard on work)
    if (!attr_done) {
        cudaFuncSetAttribute(ode_kernel,
                             cudaFuncAttributeMaxDynamicSharedMemorySize,
                             TILE_BYTES);
        attr_done = true;
    }

    const int grid = (batch + BLOCK - 1) / BLOCK;
    ode_kernel<<<grid, BLOCK, TILE_BYTES>>>(x0s, matrix, T, (float*)d_out,
                                            batch, (long long)out_size, tail);
}

// round 10
// speedup vs baseline: 1.0908x; 1.0028x over previous
#include <cuda_runtime.h>
#include <cstdint>

// NeuralODE via exact linearity: x_k = Q^k x0, Q = (Tsit5 substep)^8.
// Block computes 128 points x 25 samples into a 25.6KB smem tile, ships it
// with ONE cp.async.bulk (TMA store path, no per-thread STG). Table of Q^k
// built in PARALLEL (warp 0, lane k: binary exponentiation); x0 LDG issued
// at kernel entry so its latency hides behind the table build.

namespace {

constexpr int TRAJ  = 25;
constexpr int NSUB  = 8;
constexpr int BLOCK = 128;
constexpr int TILE_BYTES = BLOCK * TRAJ * 8;   // 25600 B (16B multiple)

struct M2 { float a, b, c, d; };

__device__ __forceinline__ M2 m2mul(const M2& x, const M2& y) {
    M2 r;
    r.a = fmaf(x.a, y.a, x.b * y.c);
    r.b = fmaf(x.a, y.b, x.b * y.d);
    r.c = fmaf(x.c, y.a, x.d * y.c);
    r.d = fmaf(x.c, y.b, x.d * y.d);
    return r;
}

__device__ __forceinline__ M2 stageY(float h, const M2* K, const float* c, int n) {
    M2 r = {1.f, 0.f, 0.f, 1.f};
    for (int i = 0; i < n; ++i) {
        float s = h * c[i];
        r.a = fmaf(s, K[i].a, r.a);
        r.b = fmaf(s, K[i].b, r.b);
        r.c = fmaf(s, K[i].c, r.c);
        r.d = fmaf(s, K[i].d, r.d);
    }
    return r;
}

__device__ __forceinline__ uint32_t smem_u32(const void* p) {
    return (uint32_t)__cvta_generic_to_shared(p);
}

__global__ void __launch_bounds__(BLOCK)
ode_kernel(const float* __restrict__ x0s,
           const float* __restrict__ matrix,
           const float* __restrict__ Tptr,
           float* __restrict__ out,
           int batch, long long out_elems, float tailval)
{
    __shared__ float4 mats[TRAJ];          // Q^k table (static, 400 B)
    extern __shared__ float2 stage[];      // 25.6 KB tile (dynamic)

    // ---- issue x0 load FIRST: latency hides behind the table build ----
    const int point = blockIdx.x * BLOCK + threadIdx.x;
    float2 xy = make_float2(0.f, 0.f);
    if (point < batch) xy = __ldg(reinterpret_cast<const float2*>(x0s) + point);

    // ---- parallel table build: warp 0, lane k computes Q^k ----
    if (threadIdx.x < 32) {
        // --- Tsit5 tableau (Tsitouras 2011) ---
        const float A21 = 0.161f;
        const float A31 = -0.008480655492356989f, A32 = 0.335480655492357f;
        const float A41 = 2.8971530571054935f, A42 = -6.359448489975075f,
                    A43 = 4.3622954328695815f;
        const float A51 = 5.325864828439257f, A52 = -11.748883564062828f,
                    A53 = 7.4955393428898365f, A54 = -0.09249506636175525f;
        const float A61 = 5.86145544294642f, A62 = -12.92096931784711f,
                    A63 = 8.159367898576159f, A64 = -0.071584973281401f,
                    A65 = -0.028269050394068383f;
        const float B1 = 0.09646076681806523f, B2 = 0.01f,
                    B3 = 0.4798896504144996f, B4 = 1.379008574103742f,
                    B5 = -3.290069515436081f, B6 = 2.324710524099774f;

        const float h = 1.0f / float((TRAJ - 1) * NSUB);
        const float T = __ldg(Tptr);
        M2 A = { T * __ldg(matrix + 0), T * __ldg(matrix + 1),
                 T * __ldg(matrix + 2), T * __ldg(matrix + 3) };

        M2 K[6];
        K[0] = A;
        { const float c[1] = {A21};                     K[1] = m2mul(A, stageY(h, K, c, 1)); }
        { const float c[2] = {A31, A32};                K[2] = m2mul(A, stageY(h, K, c, 2)); }
        { const float c[3] = {A41, A42, A43};           K[3] = m2mul(A, stageY(h, K, c, 3)); }
        { const float c[4] = {A51, A52, A53, A54};      K[4] = m2mul(A, stageY(h, K, c, 4)); }
        { const float c[5] = {A61, A62, A63, A64, A65}; K[5] = m2mul(A, stageY(h, K, c, 5)); }
        const float bb[6] = {B1, B2, B3, B4, B5, B6};
        M2 S = stageY(h, K, bb, 6);                          // one substep
        M2 Q = m2mul(S, S); Q = m2mul(Q, Q); Q = m2mul(Q, Q); // S^8

        // Lane k (k < 25): Q^k by binary exponentiation (<=5 dependent mults).
        const int k = threadIdx.x;
        if (k < TRAJ) {
            M2 R = {1.f, 0.f, 0.f, 1.f};
            M2 B = Q;
            #pragma unroll
            for (int bit = 0; bit < 5; ++bit) {
                if ((k >> bit) & 1) R = m2mul(B, R);
                if (bit < 4) B = m2mul(B, B);
            }
            mats[k] = make_float4(R.a, R.b, R.c, R.d);
        }
    }
    __syncthreads();

    // ---- stage this thread's 25 samples (uniform k -> LDS broadcast) ----
    #pragma unroll
    for (int k = 0; k < TRAJ; ++k) {
        const float4 m = mats[k];
        stage[threadIdx.x * TRAJ + k] =
            make_float2(fmaf(m.x, xy.x, m.y * xy.y),
                        fmaf(m.z, xy.x, m.w * xy.y));
    }
    __syncthreads();

    float* gdst = out + (size_t)blockIdx.x * (BLOCK * TRAJ * 2);
    const int npts = min(BLOCK, batch - blockIdx.x * BLOCK);

    if (npts == BLOCK) {
        // One bulk async copy: smem tile -> contiguous global slice.
        if (threadIdx.x == 0) {
            asm volatile("fence.proxy.async.shared::cta;" ::: "memory");
            asm volatile(
                "cp.async.bulk.global.shared::cta.bulk_group [%0], [%1], %2;"
                :: "l"(gdst), "r"(smem_u32(stage)), "n"(TILE_BYTES)
                : "memory");
            asm volatile("cp.async.bulk.commit_group;" ::: "memory");
            asm volatile("cp.async.bulk.wait_group.read 0;" ::: "memory");
        }
        __syncthreads();     // smem must stay alive until the bulk read completes
    } else if (npts > 0) {
        // Partial tail block (not hit for batch=4096*128): plain STG flush.
        const int nf4 = npts * TRAJ / 2;
        const float4* st4 = reinterpret_cast<const float4*>(stage);
        float4* g4 = reinterpret_cast<float4*>(gdst);
        for (int j = threadIdx.x; j < nf4; j += BLOCK) g4[j] = st4[j];
        if ((npts * TRAJ) & 1) {
            if (threadIdx.x == 0)
                reinterpret_cast<float2*>(gdst)[npts * TRAJ - 1] =
                    stage[npts * TRAJ - 1];
        }
    }

    // Scalar tail (num_steps analog), exactly representable in fp32.
    if (blockIdx.x == 0 && threadIdx.x == 0) {
        const long long traj_elems = (long long)batch * TRAJ * 2;
        for (long long i = traj_elems; i < out_elems; ++i) out[i] = tailval;
    }
}

} // namespace

extern "C" void kernel_launch(void* const* d_in, const int* in_sizes, int n_in,
                              void* d_out, int out_size) {
    const float* x0s    = (const float*)d_in[0];
    const float* matrix = (const float*)d_in[1];
    const float* T      = (const float*)d_in[2];

    const int batch = in_sizes[0] / 2;                 // x0s is [batch,2]
    const float tail = (float)((long long)batch * (TRAJ - 1) * NSUB);

    static bool attr_done = false;   // idempotent attribute set (not a work guard)
    if (!attr_done) {
        cudaFuncSetAttribute(ode_kernel,
                             cudaFuncAttributeMaxDynamicSharedMemorySize,
                             TILE_BYTES);
        attr_done = true;
    }

    const int grid = (batch + BLOCK - 1) / BLOCK;
    ode_kernel<<<grid, BLOCK, TILE_BYTES>>>(x0s, matrix, T, (float*)d_out,
                                            batch, (long long)out_size, tail);
}

// round 11
// speedup vs baseline: 1.1014x; 1.0097x over previous
#include <cuda_runtime.h>
#include <cstdint>

// NeuralODE via exact linearity: x_k = Q^k x0, Q = (Tsit5 substep)^8.
// Each block processes 4 tiles of 128 points with TWO ping-pong 25.6KB smem
// buffers: compute tile t+1 while tile t's cp.async.bulk (TMA store) drains.
// Buffer reuse gated by cp.async.bulk.wait_group.read 1. Table of Q^k built
// once per block in parallel (warp 0, binary exponentiation).

namespace {

constexpr int TRAJ  = 25;
constexpr int NSUB  = 8;
constexpr int BLOCK = 128;
constexpr int TILES = 4;                        // tiles per block
constexpr int TILE_F2   = BLOCK * TRAJ;         // 3200 float2 per tile
constexpr int TILE_BYTES = TILE_F2 * 8;         // 25600 B
constexpr int SMEM_BYTES = 2 * TILE_BYTES;      // 51200 B ping-pong

struct M2 { float a, b, c, d; };

__device__ __forceinline__ M2 m2mul(const M2& x, const M2& y) {
    M2 r;
    r.a = fmaf(x.a, y.a, x.b * y.c);
    r.b = fmaf(x.a, y.b, x.b * y.d);
    r.c = fmaf(x.c, y.a, x.d * y.c);
    r.d = fmaf(x.c, y.b, x.d * y.d);
    return r;
}

__device__ __forceinline__ M2 stageY(float h, const M2* K, const float* c, int n) {
    M2 r = {1.f, 0.f, 0.f, 1.f};
    for (int i = 0; i < n; ++i) {
        float s = h * c[i];
        r.a = fmaf(s, K[i].a, r.a);
        r.b = fmaf(s, K[i].b, r.b);
        r.c = fmaf(s, K[i].c, r.c);
        r.d = fmaf(s, K[i].d, r.d);
    }
    return r;
}

__device__ __forceinline__ uint32_t smem_u32(const void* p) {
    return (uint32_t)__cvta_generic_to_shared(p);
}

__global__ void __launch_bounds__(BLOCK)
ode_kernel(const float* __restrict__ x0s,
           const float* __restrict__ matrix,
           const float* __restrict__ Tptr,
           float* __restrict__ out,
           int batch, long long out_elems, float tailval)
{
    __shared__ float4 mats[TRAJ];          // Q^k table (static, 400 B)
    extern __shared__ float2 stage[];      // 2 x 25.6 KB ping-pong (dynamic)

    const float2* __restrict__ x02 = reinterpret_cast<const float2*>(x0s);
    const int tile0 = blockIdx.x * TILES;

    // ---- prefetch first tile's x0 (hides behind the table build) ----
    const int p0 = tile0 * BLOCK + threadIdx.x;
    float2 xy = make_float2(0.f, 0.f);
    if (p0 < batch) xy = __ldg(&x02[p0]);

    // ---- parallel table build: warp 0, lane k computes Q^k ----
    if (threadIdx.x < 32) {
        // --- Tsit5 tableau (Tsitouras 2011) ---
        const float A21 = 0.161f;
        const float A31 = -0.008480655492356989f, A32 = 0.335480655492357f;
        const float A41 = 2.8971530571054935f, A42 = -6.359448489975075f,
                    A43 = 4.3622954328695815f;
        const float A51 = 5.325864828439257f, A52 = -11.748883564062828f,
                    A53 = 7.4955393428898365f, A54 = -0.09249506636175525f;
        const float A61 = 5.86145544294642f, A62 = -12.92096931784711f,
                    A63 = 8.159367898576159f, A64 = -0.071584973281401f,
                    A65 = -0.028269050394068383f;
        const float B1 = 0.09646076681806523f, B2 = 0.01f,
                    B3 = 0.4798896504144996f, B4 = 1.379008574103742f,
                    B5 = -3.290069515436081f, B6 = 2.324710524099774f;

        const float h = 1.0f / float((TRAJ - 1) * NSUB);
        const float T = __ldg(Tptr);
        M2 A = { T * __ldg(matrix + 0), T * __ldg(matrix + 1),
                 T * __ldg(matrix + 2), T * __ldg(matrix + 3) };

        M2 K[6];
        K[0] = A;
        { const float c[1] = {A21};                     K[1] = m2mul(A, stageY(h, K, c, 1)); }
        { const float c[2] = {A31, A32};                K[2] = m2mul(A, stageY(h, K, c, 2)); }
        { const float c[3] = {A41, A42, A43};           K[3] = m2mul(A, stageY(h, K, c, 3)); }
        { const float c[4] = {A51, A52, A53, A54};      K[4] = m2mul(A, stageY(h, K, c, 4)); }
        { const float c[5] = {A61, A62, A63, A64, A65}; K[5] = m2mul(A, stageY(h, K, c, 5)); }
        const float bb[6] = {B1, B2, B3, B4, B5, B6};
        M2 S = stageY(h, K, bb, 6);                          // one substep
        M2 Q = m2mul(S, S); Q = m2mul(Q, Q); Q = m2mul(Q, Q); // S^8

        const int k = threadIdx.x;
        if (k < TRAJ) {                     // Q^k via binary exponentiation
            M2 R = {1.f, 0.f, 0.f, 1.f};
            M2 B = Q;
            #pragma unroll
            for (int bit = 0; bit < 5; ++bit) {
                if ((k >> bit) & 1) R = m2mul(B, R);
                if (bit < 4) B = m2mul(B, B);
            }
            mats[k] = make_float4(R.a, R.b, R.c, R.d);
        }
    }
    __syncthreads();

    #pragma unroll 1
    for (int t = 0; t < TILES; ++t) {
        const int tile = tile0 + t;
        const int pbase = tile * BLOCK;
        if (pbase >= batch) break;

        // Buffer reuse gate: at most 1 pending TMA group -> buffer (t&1) free.
        if (t >= 2) {
            if (threadIdx.x == 0)
                asm volatile("cp.async.bulk.wait_group.read 1;" ::: "memory");
            __syncthreads();
        }

        float2* buf = stage + (t & 1) * TILE_F2;

        // x0 for this tile (t==0 already prefetched).
        if (t > 0) {
            const int p = pbase + threadIdx.x;
            xy = make_float2(0.f, 0.f);
            if (p < batch) xy = __ldg(&x02[p]);
        }

        // Stage this thread's 25 samples (uniform k -> LDS broadcast).
        #pragma unroll
        for (int k = 0; k < TRAJ; ++k) {
            const float4 m = mats[k];
            buf[threadIdx.x * TRAJ + k] =
                make_float2(fmaf(m.x, xy.x, m.y * xy.y),
                            fmaf(m.z, xy.x, m.w * xy.y));
        }
        __syncthreads();

        float* gdst = out + (size_t)tile * (BLOCK * TRAJ * 2);
        const int npts = min(BLOCK, batch - pbase);

        if (npts == BLOCK) {
            if (threadIdx.x == 0) {
                asm volatile("fence.proxy.async.shared::cta;" ::: "memory");
                asm volatile(
                    "cp.async.bulk.global.shared::cta.bulk_group [%0], [%1], %2;"
                    :: "l"(gdst), "r"(smem_u32(buf)), "n"(TILE_BYTES)
                    : "memory");
                asm volatile("cp.async.bulk.commit_group;" ::: "memory");
            }
            // NO wait here: drain overlaps the next tile's compute.
        } else {
            // Partial tail tile (not hit for batch = 4096*128): STG flush.
            const int nf4 = npts * TRAJ / 2;
            const float4* st4 = reinterpret_cast<const float4*>(buf);
            float4* g4 = reinterpret_cast<float4*>(gdst);
            for (int j = threadIdx.x; j < nf4; j += BLOCK) g4[j] = st4[j];
            if ((npts * TRAJ) & 1) {
                if (threadIdx.x == 0)
                    reinterpret_cast<float2*>(gdst)[npts * TRAJ - 1] =
                        buf[npts * TRAJ - 1];
            }
            __syncthreads();
        }
    }

    // Drain all pending TMA groups before smem is released.
    if (threadIdx.x == 0)
        asm volatile("cp.async.bulk.wait_group.read 0;" ::: "memory");
    __syncthreads();

    // Scalar tail (num_steps analog), exactly representable in fp32.
    if (blockIdx.x == 0 && threadIdx.x == 0) {
        const long long traj_elems = (long long)batch * TRAJ * 2;
        for (long long i = traj_elems; i < out_elems; ++i) out[i] = tailval;
    }
}

} // namespace

extern "C" void kernel_launch(void* const* d_in, const int* in_sizes, int n_in,
                              void* d_out, int out_size) {
    const float* x0s    = (const float*)d_in[0];
    const float* matrix = (const float*)d_in[1];
    const float* T      = (const float*)d_in[2];

    const int batch = in_sizes[0] / 2;                 // x0s is [batch,2]
    const float tail = (float)((long long)batch * (TRAJ - 1) * NSUB);

    static bool attr_done = false;   // idempotent attribute set (not a work guard)
    if (!attr_done) {
        cudaFuncSetAttribute(ode_kernel,
                             cudaFuncAttributeMaxDynamicSharedMemorySize,
                             SMEM_BYTES);
        attr_done = true;
    }

    const int pts_per_block = BLOCK * TILES;
    const int grid = (batch + pts_per_block - 1) / pts_per_block;

    ode_kernel<<<grid, BLOCK, SMEM_BYTES>>>(x0s, matrix, T, (float*)d_out,
                                            batch, (long long)out_size, tail);
}

// round 12
// speedup vs baseline: 1.2107x; 1.0992x over previous
#include <cuda_runtime.h>
#include <cstdint>

// NeuralODE via exact linearity: x_k = Q^k x0, Q = (Tsit5 substep)^8.
// R10 structure (best kernel time): 128-point/25.6KB tile per block, one
// cp.async.bulk TMA store per block. NEW: stores carry an L2::evict_first
// cache policy so the steady-state graph-replay loop write-backs stream
// smoothly instead of bursting on the next replay's write-allocates.

namespace {

constexpr int TRAJ  = 25;
constexpr int NSUB  = 8;
constexpr int BLOCK = 128;
constexpr int TILE_BYTES = BLOCK * TRAJ * 8;   // 25600 B (16B multiple)

struct M2 { float a, b, c, d; };

__device__ __forceinline__ M2 m2mul(const M2& x, const M2& y) {
    M2 r;
    r.a = fmaf(x.a, y.a, x.b * y.c);
    r.b = fmaf(x.a, y.b, x.b * y.d);
    r.c = fmaf(x.c, y.a, x.d * y.c);
    r.d = fmaf(x.c, y.b, x.d * y.d);
    return r;
}

__device__ __forceinline__ M2 stageY(float h, const M2* K, const float* c, int n) {
    M2 r = {1.f, 0.f, 0.f, 1.f};
    for (int i = 0; i < n; ++i) {
        float s = h * c[i];
        r.a = fmaf(s, K[i].a, r.a);
        r.b = fmaf(s, K[i].b, r.b);
        r.c = fmaf(s, K[i].c, r.c);
        r.d = fmaf(s, K[i].d, r.d);
    }
    return r;
}

__device__ __forceinline__ uint32_t smem_u32(const void* p) {
    return (uint32_t)__cvta_generic_to_shared(p);
}

__global__ void __launch_bounds__(BLOCK)
ode_kernel(const float* __restrict__ x0s,
           const float* __restrict__ matrix,
           const float* __restrict__ Tptr,
           float* __restrict__ out,
           int batch, long long out_elems, float tailval)
{
    __shared__ float4 mats[TRAJ];          // Q^k table (static, 400 B)
    extern __shared__ float2 stage[];      // 25.6 KB tile (dynamic)

    // ---- issue x0 load FIRST: latency hides behind the table build ----
    const int point = blockIdx.x * BLOCK + threadIdx.x;
    float2 xy = make_float2(0.f, 0.f);
    if (point < batch) xy = __ldg(reinterpret_cast<const float2*>(x0s) + point);

    // ---- parallel table build: warp 0, lane k computes Q^k ----
    if (threadIdx.x < 32) {
        // --- Tsit5 tableau (Tsitouras 2011) ---
        const float A21 = 0.161f;
        const float A31 = -0.008480655492356989f, A32 = 0.335480655492357f;
        const float A41 = 2.8971530571054935f, A42 = -6.359448489975075f,
                    A43 = 4.3622954328695815f;
        const float A51 = 5.325864828439257f, A52 = -11.748883564062828f,
                    A53 = 7.4955393428898365f, A54 = -0.09249506636175525f;
        const float A61 = 5.86145544294642f, A62 = -12.92096931784711f,
                    A63 = 8.159367898576159f, A64 = -0.071584973281401f,
                    A65 = -0.028269050394068383f;
        const float B1 = 0.09646076681806523f, B2 = 0.01f,
                    B3 = 0.4798896504144996f, B4 = 1.379008574103742f,
                    B5 = -3.290069515436081f, B6 = 2.324710524099774f;

        const float h = 1.0f / float((TRAJ - 1) * NSUB);
        const float T = __ldg(Tptr);
        M2 A = { T * __ldg(matrix + 0), T * __ldg(matrix + 1),
                 T * __ldg(matrix + 2), T * __ldg(matrix + 3) };

        M2 K[6];
        K[0] = A;
        { const float c[1] = {A21};                     K[1] = m2mul(A, stageY(h, K, c, 1)); }
        { const float c[2] = {A31, A32};                K[2] = m2mul(A, stageY(h, K, c, 2)); }
        { const float c[3] = {A41, A42, A43};           K[3] = m2mul(A, stageY(h, K, c, 3)); }
        { const float c[4] = {A51, A52, A53, A54};      K[4] = m2mul(A, stageY(h, K, c, 4)); }
        { const float c[5] = {A61, A62, A63, A64, A65}; K[5] = m2mul(A, stageY(h, K, c, 5)); }
        const float bb[6] = {B1, B2, B3, B4, B5, B6};
        M2 S = stageY(h, K, bb, 6);                          // one substep
        M2 Q = m2mul(S, S); Q = m2mul(Q, Q); Q = m2mul(Q, Q); // S^8

        const int k = threadIdx.x;
        if (k < TRAJ) {                     // Q^k via binary exponentiation
            M2 R = {1.f, 0.f, 0.f, 1.f};
            M2 B = Q;
            #pragma unroll
            for (int bit = 0; bit < 5; ++bit) {
                if ((k >> bit) & 1) R = m2mul(B, R);
                if (bit < 4) B = m2mul(B, B);
            }
            mats[k] = make_float4(R.a, R.b, R.c, R.d);
        }
    }
    __syncthreads();

    // ---- stage this thread's 25 samples (uniform k -> LDS broadcast) ----
    #pragma unroll
    for (int k = 0; k < TRAJ; ++k) {
        const float4 m = mats[k];
        stage[threadIdx.x * TRAJ + k] =
            make_float2(fmaf(m.x, xy.x, m.y * xy.y),
                        fmaf(m.z, xy.x, m.w * xy.y));
    }
    __syncthreads();

    float* gdst = out + (size_t)blockIdx.x * (BLOCK * TRAJ * 2);
    const int npts = min(BLOCK, batch - blockIdx.x * BLOCK);

    if (npts == BLOCK) {
        // One bulk async copy with L2::evict_first policy: the output is
        // never re-read by this kernel, so queue it for early write-back.
        if (threadIdx.x == 0) {
            uint64_t policy;
            asm volatile("createpolicy.fractional.L2::evict_first.b64 %0, 1.0;"
                         : "=l"(policy));
            asm volatile("fence.proxy.async.shared::cta;" ::: "memory");
            asm volatile(
                "cp.async.bulk.global.shared::cta.bulk_group.L2::cache_hint "
                "[%0], [%1], %2, %3;"
                :: "l"(gdst), "r"(smem_u32(stage)), "n"(TILE_BYTES), "l"(policy)
                : "memory");
            asm volatile("cp.async.bulk.commit_group;" ::: "memory");
            asm volatile("cp.async.bulk.wait_group.read 0;" ::: "memory");
        }
        __syncthreads();     // smem must stay alive until the bulk read completes
    } else if (npts > 0) {
        // Partial tail block (not hit for batch=4096*128): streaming STG flush.
        const int nf4 = npts * TRAJ / 2;
        const float4* st4 = reinterpret_cast<const float4*>(stage);
        float4* g4 = reinterpret_cast<float4*>(gdst);
        for (int j = threadIdx.x; j < nf4; j += BLOCK) {
            const float4 v = st4[j];
            __stcs(&g4[j], v);
        }
        if ((npts * TRAJ) & 1) {
            if (threadIdx.x == 0) {
                const float2 v = stage[npts * TRAJ - 1];
                __stcs(&reinterpret_cast<float2*>(gdst)[npts * TRAJ - 1], v);
            }
        }
    }

    // Scalar tail (num_steps analog), exactly representable in fp32.
    if (blockIdx.x == 0 && threadIdx.x == 0) {
        const long long traj_elems = (long long)batch * TRAJ * 2;
        for (long long i = traj_elems; i < out_elems; ++i) out[i] = tailval;
    }
}

} // namespace

extern "C" void kernel_launch(void* const* d_in, const int* in_sizes, int n_in,
                              void* d_out, int out_size) {
    const float* x0s    = (const float*)d_in[0];
    const float* matrix = (const float*)d_in[1];
    const float* T      = (const float*)d_in[2];

    const int batch = in_sizes[0] / 2;                 // x0s is [batch,2]
    const float tail = (float)((long long)batch * (TRAJ - 1) * NSUB);

    static bool attr_done = false;   // idempotent attribute set (not a work guard)
    if (!attr_done) {
        cudaFuncSetAttribute(ode_kernel,
                             cudaFuncAttributeMaxDynamicSharedMemorySize,
                             TILE_BYTES);
        attr_done = true;
    }

    const int grid = (batch + BLOCK - 1) / BLOCK;
    ode_kernel<<<grid, BLOCK, TILE_BYTES>>>(x0s, matrix, T, (float*)d_out,
                                            batch, (long long)out_size, tail);
}